// round 7
// baseline (speedup 1.0000x reference)
#include <cuda_runtime.h>
#include <cuda_bf16.h>
#include <cstdint>

#define BB 2
#define NN 2048
#define DD 64
#define TI 128
#define TJ 128

// ---------------- smem layout ----------------
#define OFF_XN      0              // 128 floats
#define OFF_YN      512            // 128 floats
#define OFF_TILES   1024
#define SUB_BYTES   (128 * 128)    // one bf16 subtile: 128 rows x 128B (64 bf16)
#define OFF_AXH     (OFF_TILES + 0 * SUB_BYTES)
#define OFF_AXL     (OFF_TILES + 1 * SUB_BYTES)
#define OFF_BYH     (OFF_TILES + 2 * SUB_BYTES)
#define OFF_BYL     (OFF_TILES + 3 * SUB_BYTES)
#define SMEM_BYTES  (OFF_TILES + 4 * SUB_BYTES)   // 66560

__device__ float g_xn[BB * NN];
__device__ float g_yn[BB * NN];

__device__ __forceinline__ uint32_t smem_u32(const void* p) {
    uint32_t a;
    asm("{ .reg .u64 t; cvta.to.shared.u64 t, %1; cvt.u32.u64 %0, t; }" : "=r"(a) : "l"(p));
    return a;
}
#define SW128(off) ((off) ^ (((off) >> 3) & 0x70))

__device__ __forceinline__ void ldsm4(uint32_t* r, uint32_t addr) {
    asm volatile("ldmatrix.sync.aligned.m8n8.x4.shared.b16 {%0,%1,%2,%3}, [%4];"
        : "=r"(r[0]), "=r"(r[1]), "=r"(r[2]), "=r"(r[3]) : "r"(addr));
}

__device__ __forceinline__ void mma16816(float* c, const uint32_t* a,
                                         uint32_t b0, uint32_t b1) {
    asm volatile("mma.sync.aligned.m16n8k16.row.col.f32.bf16.bf16.f32 "
        "{%0,%1,%2,%3}, {%4,%5,%6,%7}, {%8,%9}, {%0,%1,%2,%3};"
        : "+f"(c[0]), "+f"(c[1]), "+f"(c[2]), "+f"(c[3])
        : "r"(a[0]), "r"(a[1]), "r"(a[2]), "r"(a[3]), "r"(b0), "r"(b1));
}

// ---------------------------------------------------------------------------
// Row squared-norms (fp32, exact): one warp per row.
// ---------------------------------------------------------------------------
__global__ void norm_kernel(const float* __restrict__ x, const float* __restrict__ y) {
    int gw = (blockIdx.x * blockDim.x + threadIdx.x) >> 5;
    int lane = threadIdx.x & 31;
    const float* src = (gw < BB * NN) ? x : y;
    float* dst = (gw < BB * NN) ? g_xn : g_yn;
    int row = gw & (BB * NN - 1);
    const float* p = src + (size_t)row * DD;
    float v0 = p[lane], v1 = p[lane + 32];
    float s = v0 * v0 + v1 * v1;
    #pragma unroll
    for (int o = 16; o; o >>= 1) s += __shfl_xor_sync(0xffffffffu, s, o);
    if (lane == 0) dst[row] = s;
}

// ---------------------------------------------------------------------------
// Main: 128x128 tile per CTA. bf16-split GEMM (K'=192) on HMMA (mma.sync).
// ---------------------------------------------------------------------------
__global__ __launch_bounds__(256, 2)
void pd_kernel(const float* __restrict__ x, const float* __restrict__ y,
               float* __restrict__ out) {
    extern __shared__ char smem[];
    uint32_t sb = smem_u32(smem);
    int tid = threadIdx.x;
    int wid = tid >> 5;
    int lane = tid & 31;
    int b = blockIdx.z;
    int i0 = blockIdx.y * TI;
    int j0 = blockIdx.x * TJ;

    // ---- load fp32 rows, convert to bf16 high/low, STS into SW128 subtiles ----
    const float4* xg = (const float4*)(x + ((size_t)b * NN + i0) * DD);
    const float4* yg = (const float4*)(y + ((size_t)b * NN + j0) * DD);
    #pragma unroll
    for (int it = 0; it < 8; it++) {
        int idx = tid + it * 256;          // 2048 float4 = 128 rows x 16
        int row = idx >> 4;
        int k4 = (idx & 15) << 2;
        uint32_t off = SW128((uint32_t)(row * 128 + k4 * 2));

        float4 v = xg[idx];
        __nv_bfloat162 h0 = __floats2bfloat162_rn(v.x, v.y);
        __nv_bfloat162 h1 = __floats2bfloat162_rn(v.z, v.w);
        __nv_bfloat162 l0 = __floats2bfloat162_rn(v.x - __bfloat162float(h0.x),
                                                  v.y - __bfloat162float(h0.y));
        __nv_bfloat162 l1 = __floats2bfloat162_rn(v.z - __bfloat162float(h1.x),
                                                  v.w - __bfloat162float(h1.y));
        *(uint2*)(smem + OFF_AXH + off) = make_uint2(*(uint32_t*)&h0, *(uint32_t*)&h1);
        *(uint2*)(smem + OFF_AXL + off) = make_uint2(*(uint32_t*)&l0, *(uint32_t*)&l1);

        float4 w = yg[idx];
        __nv_bfloat162 g0 = __floats2bfloat162_rn(w.x, w.y);
        __nv_bfloat162 g1 = __floats2bfloat162_rn(w.z, w.w);
        __nv_bfloat162 m0 = __floats2bfloat162_rn(w.x - __bfloat162float(g0.x),
                                                  w.y - __bfloat162float(g0.y));
        __nv_bfloat162 m1 = __floats2bfloat162_rn(w.z - __bfloat162float(g1.x),
                                                  w.w - __bfloat162float(g1.y));
        *(uint2*)(smem + OFF_BYH + off) = make_uint2(*(uint32_t*)&g0, *(uint32_t*)&g1);
        *(uint2*)(smem + OFF_BYL + off) = make_uint2(*(uint32_t*)&m0, *(uint32_t*)&m1);
    }

    if (tid < 128)
        ((float*)(smem + OFF_XN))[tid] = g_xn[b * NN + i0 + tid];
    else
        ((float*)(smem + OFF_YN))[tid - 128] = g_yn[b * NN + j0 + tid - 128];
    __syncthreads();

    // ---- warp tiling: warp (mw, nw) computes rows mw*32..+31, cols nw*64..+63 ----
    int mw = wid & 3;
    int nw = wid >> 2;

    // ldmatrix lane addressing (lane-constant parts).
    // A .x4: matrix mi = lane>>3; row = m0 + (lane&7) + (mi&1)*8; kbyte += (mi>>1)*16
    uint32_t rA[2], mskA[2];
    #pragma unroll
    for (int mt = 0; mt < 2; mt++) {
        uint32_t row = mw * 32 + mt * 16 + (lane & 7) + ((lane >> 3) & 1) * 8;
        rA[mt] = row * 128;
        mskA[mt] = (rA[mt] >> 3) & 0x70;
    }
    uint32_t kA = (lane >> 4) * 16;
    // B .x4: matrix mi = lane>>3; nrow = n0 + (lane&7) + (mi>>1)*8; kbyte += (mi&1)*16
    uint32_t rB[4], mskB[4];
    #pragma unroll
    for (int np = 0; np < 4; np++) {
        uint32_t row = nw * 64 + np * 16 + (lane & 7) + ((lane >> 4) & 1) * 8;
        rB[np] = row * 128;
        mskB[np] = (rB[np] >> 3) & 0x70;
    }
    uint32_t kB = ((lane >> 3) & 1) * 16;

    float acc[2][8][4];
    #pragma unroll
    for (int mt = 0; mt < 2; mt++)
        #pragma unroll
        for (int nt = 0; nt < 8; nt++)
            #pragma unroll
            for (int q = 0; q < 4; q++) acc[mt][nt][q] = 0.f;

    // ---- 12 k-steps: s0-3 xh*yh, s4-7 xh*yl, s8-11 xl*yh ----
    #pragma unroll
    for (int s = 0; s < 12; s++) {
        uint32_t abase = sb + ((s < 8) ? OFF_AXH : OFF_AXL);
        uint32_t bbase = sb + ((s < 4) ? OFF_BYH : (s < 8) ? OFF_BYL : OFF_BYH);
        uint32_t kb = (uint32_t)(s & 3) * 32;

        uint32_t afr[2][4];
        #pragma unroll
        for (int mt = 0; mt < 2; mt++)
            ldsm4(afr[mt], abase + rA[mt] + ((kb + kA) ^ mskA[mt]));

        uint32_t bfr[4][4];
        #pragma unroll
        for (int np = 0; np < 4; np++)
            ldsm4(bfr[np], bbase + rB[np] + ((kb + kB) ^ mskB[np]));

        #pragma unroll
        for (int mt = 0; mt < 2; mt++)
            #pragma unroll
            for (int np = 0; np < 4; np++) {
                mma16816(acc[mt][2 * np],     afr[mt], bfr[np][0], bfr[np][1]);
                mma16816(acc[mt][2 * np + 1], afr[mt], bfr[np][2], bfr[np][3]);
            }
    }

    // ---- epilogue: out = xn + yn - 2*dot, direct STG.64 (full 32B sectors) ----
    int g = lane >> 2;
    int tq = lane & 3;
    const float* xns = (const float*)(smem + OFF_XN);
    const float* yns = (const float*)(smem + OFF_YN);

    #pragma unroll
    for (int mt = 0; mt < 2; mt++) {
        int rlo = mw * 32 + mt * 16 + g;
        float xn_lo = xns[rlo];
        float xn_hi = xns[rlo + 8];
        float* out_lo = out + ((size_t)(b * NN + i0 + rlo)) * NN + j0;
        float* out_hi = out_lo + (size_t)8 * NN;
        #pragma unroll
        for (int nt = 0; nt < 8; nt++) {
            int jl = nw * 64 + nt * 8 + tq * 2;
            float yn0 = yns[jl], yn1 = yns[jl + 1];
            float* a4 = acc[mt][nt];
            float2 v;
            v.x = fmaf(-2.f, a4[0], xn_lo + yn0);
            v.y = fmaf(-2.f, a4[1], xn_lo + yn1);
            *(float2*)(out_lo + jl) = v;
            v.x = fmaf(-2.f, a4[2], xn_hi + yn0);
            v.y = fmaf(-2.f, a4[3], xn_hi + yn1);
            *(float2*)(out_hi + jl) = v;
        }
    }
}

extern "C" void kernel_launch(void* const* d_in, const int* in_sizes, int n_in,
                              void* d_out, int out_size) {
    const float* x = (const float*)d_in[0];
    const float* y = (const float*)d_in[1];
    float* out = (float*)d_out;

    cudaFuncSetAttribute(pd_kernel, cudaFuncAttributeMaxDynamicSharedMemorySize,
                         (int)SMEM_BYTES);

    norm_kernel<<<(2 * BB * NN * 32) / 256, 256>>>(x, y);

    dim3 grid(NN / TJ, NN / TI, BB);
    pd_kernel<<<grid, 256, SMEM_BYTES>>>(x, y, out);
}

// round 8
// speedup vs baseline: 1.2379x; 1.2379x over previous
#include <cuda_runtime.h>
#include <cuda_bf16.h>
#include <cstdint>

#define BB 2
#define NN 2048
#define DD 64
#define TI 128
#define TJ 128

// ---------------- smem layout ----------------
#define OFF_XN      0              // 128 floats
#define OFF_YN      512            // 128 floats
#define OFF_TILES   1024
#define SUB_BYTES   (128 * 128)    // one bf16 subtile: 128 rows x 128B (64 bf16)
#define OFF_AXH     (OFF_TILES + 0 * SUB_BYTES)
#define OFF_AXL     (OFF_TILES + 1 * SUB_BYTES)
#define OFF_BYH     (OFF_TILES + 2 * SUB_BYTES)
#define OFF_BYL     (OFF_TILES + 3 * SUB_BYTES)
#define SMEM_BYTES  (OFF_TILES + 4 * SUB_BYTES)   // 66560

__device__ float g_xn[BB * NN];
__device__ float g_yn[BB * NN];

__device__ __forceinline__ uint32_t smem_u32(const void* p) {
    uint32_t a;
    asm("{ .reg .u64 t; cvta.to.shared.u64 t, %1; cvt.u32.u64 %0, t; }" : "=r"(a) : "l"(p));
    return a;
}
#define SW128(off) ((off) ^ (((off) >> 3) & 0x70))

__device__ __forceinline__ void ldsm4(uint32_t* r, uint32_t addr) {
    asm volatile("ldmatrix.sync.aligned.m8n8.x4.shared.b16 {%0,%1,%2,%3}, [%4];"
        : "=r"(r[0]), "=r"(r[1]), "=r"(r[2]), "=r"(r[3]) : "r"(addr));
}

__device__ __forceinline__ void mma16816(float* c, const uint32_t* a,
                                         uint32_t b0, uint32_t b1) {
    asm volatile("mma.sync.aligned.m16n8k16.row.col.f32.bf16.bf16.f32 "
        "{%0,%1,%2,%3}, {%4,%5,%6,%7}, {%8,%9}, {%0,%1,%2,%3};"
        : "+f"(c[0]), "+f"(c[1]), "+f"(c[2]), "+f"(c[3])
        : "r"(a[0]), "r"(a[1]), "r"(a[2]), "r"(a[3]), "r"(b0), "r"(b1));
}

// ---------------------------------------------------------------------------
// Row squared-norms (fp32, exact): one warp per row.
// ---------------------------------------------------------------------------
__global__ void norm_kernel(const float* __restrict__ x, const float* __restrict__ y) {
    int gw = (blockIdx.x * blockDim.x + threadIdx.x) >> 5;
    int lane = threadIdx.x & 31;
    const float* src = (gw < BB * NN) ? x : y;
    float* dst = (gw < BB * NN) ? g_xn : g_yn;
    int row = gw & (BB * NN - 1);
    const float* p = src + (size_t)row * DD;
    float v0 = p[lane], v1 = p[lane + 32];
    float s = v0 * v0 + v1 * v1;
    #pragma unroll
    for (int o = 16; o; o >>= 1) s += __shfl_xor_sync(0xffffffffu, s, o);
    if (lane == 0) dst[row] = s;
}

// ---------------------------------------------------------------------------
// Main: 128x128 tile per CTA. bf16-split GEMM (K'=192) on HMMA (mma.sync).
// kb-outer loop: load each kb-panel's fragments ONCE, run all 3 product
// phases against them (48 ldsm total instead of 72).
// ---------------------------------------------------------------------------
__global__ __launch_bounds__(256, 2)
void pd_kernel(const float* __restrict__ x, const float* __restrict__ y,
               float* __restrict__ out) {
    extern __shared__ char smem[];
    uint32_t sb = smem_u32(smem);
    int tid = threadIdx.x;
    int wid = tid >> 5;
    int lane = tid & 31;
    int b = blockIdx.z;
    int i0 = blockIdx.y * TI;
    int j0 = blockIdx.x * TJ;

    // ---- load fp32 rows, convert to bf16 high/low, STS into SW128 subtiles ----
    const float4* xg = (const float4*)(x + ((size_t)b * NN + i0) * DD);
    const float4* yg = (const float4*)(y + ((size_t)b * NN + j0) * DD);
    #pragma unroll
    for (int it = 0; it < 8; it++) {
        int idx = tid + it * 256;          // 2048 float4 = 128 rows x 16
        int row = idx >> 4;
        int k4 = (idx & 15) << 2;
        uint32_t off = SW128((uint32_t)(row * 128 + k4 * 2));

        float4 v = xg[idx];
        __nv_bfloat162 h0 = __floats2bfloat162_rn(v.x, v.y);
        __nv_bfloat162 h1 = __floats2bfloat162_rn(v.z, v.w);
        __nv_bfloat162 l0 = __floats2bfloat162_rn(v.x - __bfloat162float(h0.x),
                                                  v.y - __bfloat162float(h0.y));
        __nv_bfloat162 l1 = __floats2bfloat162_rn(v.z - __bfloat162float(h1.x),
                                                  v.w - __bfloat162float(h1.y));
        *(uint2*)(smem + OFF_AXH + off) = make_uint2(*(uint32_t*)&h0, *(uint32_t*)&h1);
        *(uint2*)(smem + OFF_AXL + off) = make_uint2(*(uint32_t*)&l0, *(uint32_t*)&l1);

        float4 w = yg[idx];
        __nv_bfloat162 g0 = __floats2bfloat162_rn(w.x, w.y);
        __nv_bfloat162 g1 = __floats2bfloat162_rn(w.z, w.w);
        __nv_bfloat162 m0 = __floats2bfloat162_rn(w.x - __bfloat162float(g0.x),
                                                  w.y - __bfloat162float(g0.y));
        __nv_bfloat162 m1 = __floats2bfloat162_rn(w.z - __bfloat162float(g1.x),
                                                  w.w - __bfloat162float(g1.y));
        *(uint2*)(smem + OFF_BYH + off) = make_uint2(*(uint32_t*)&g0, *(uint32_t*)&g1);
        *(uint2*)(smem + OFF_BYL + off) = make_uint2(*(uint32_t*)&m0, *(uint32_t*)&m1);
    }

    if (tid < 128)
        ((float*)(smem + OFF_XN))[tid] = g_xn[b * NN + i0 + tid];
    else
        ((float*)(smem + OFF_YN))[tid - 128] = g_yn[b * NN + j0 + tid - 128];
    __syncthreads();

    // ---- warp tiling: warp (mw, nw) computes rows mw*32..+31, cols nw*64..+63 ----
    int mw = wid & 3;
    int nw = wid >> 2;

    // ldmatrix lane addressing (lane-constant parts).
    // A .x4: matrix mi = lane>>3; row = m0 + (lane&7) + (mi&1)*8; kbyte += (mi>>1)*16
    uint32_t rA[2], mskA[2];
    #pragma unroll
    for (int mt = 0; mt < 2; mt++) {
        uint32_t row = mw * 32 + mt * 16 + (lane & 7) + ((lane >> 3) & 1) * 8;
        rA[mt] = row * 128;
        mskA[mt] = (rA[mt] >> 3) & 0x70;
    }
    uint32_t kA = (lane >> 4) * 16;
    // B .x4: matrix mi = lane>>3; nrow = n0 + (lane&7) + (mi>>1)*8; kbyte += (mi&1)*16
    uint32_t rB[4], mskB[4];
    #pragma unroll
    for (int np = 0; np < 4; np++) {
        uint32_t row = nw * 64 + np * 16 + (lane & 7) + ((lane >> 4) & 1) * 8;
        rB[np] = row * 128;
        mskB[np] = (rB[np] >> 3) & 0x70;
    }
    uint32_t kB = ((lane >> 3) & 1) * 16;

    float acc[2][8][4];
    #pragma unroll
    for (int mt = 0; mt < 2; mt++)
        #pragma unroll
        for (int nt = 0; nt < 8; nt++)
            #pragma unroll
            for (int q = 0; q < 4; q++) acc[mt][nt][q] = 0.f;

    // ---- kb-outer: per 16-wide k-panel, 12 unique ldsm then 48 HMMA ----
    #pragma unroll
    for (int kb = 0; kb < 4; kb++) {
        uint32_t kbyte = (uint32_t)kb * 32;

        uint32_t axh[2][4], axl[2][4];
        #pragma unroll
        for (int mt = 0; mt < 2; mt++) {
            uint32_t ko = (kbyte + kA);
            ldsm4(axh[mt], sb + OFF_AXH + rA[mt] + (ko ^ mskA[mt]));
            ldsm4(axl[mt], sb + OFF_AXL + rA[mt] + (ko ^ mskA[mt]));
        }
        uint32_t byh[4][4], byl[4][4];
        #pragma unroll
        for (int np = 0; np < 4; np++) {
            uint32_t ko = (kbyte + kB);
            ldsm4(byh[np], sb + OFF_BYH + rB[np] + (ko ^ mskB[np]));
            ldsm4(byl[np], sb + OFF_BYL + rB[np] + (ko ^ mskB[np]));
        }

        // phase 1: xh . yh
        #pragma unroll
        for (int mt = 0; mt < 2; mt++)
            #pragma unroll
            for (int np = 0; np < 4; np++) {
                mma16816(acc[mt][2 * np],     axh[mt], byh[np][0], byh[np][1]);
                mma16816(acc[mt][2 * np + 1], axh[mt], byh[np][2], byh[np][3]);
            }
        // phase 2: xh . yl
        #pragma unroll
        for (int mt = 0; mt < 2; mt++)
            #pragma unroll
            for (int np = 0; np < 4; np++) {
                mma16816(acc[mt][2 * np],     axh[mt], byl[np][0], byl[np][1]);
                mma16816(acc[mt][2 * np + 1], axh[mt], byl[np][2], byl[np][3]);
            }
        // phase 3: xl . yh
        #pragma unroll
        for (int mt = 0; mt < 2; mt++)
            #pragma unroll
            for (int np = 0; np < 4; np++) {
                mma16816(acc[mt][2 * np],     axl[mt], byh[np][0], byh[np][1]);
                mma16816(acc[mt][2 * np + 1], axl[mt], byh[np][2], byh[np][3]);
            }
    }

    // ---- epilogue: out = xn + yn - 2*dot, direct STG.64 ----
    int g = lane >> 2;
    int tq = lane & 3;
    const float* xns = (const float*)(smem + OFF_XN);
    const float* yns = (const float*)(smem + OFF_YN);

    #pragma unroll
    for (int mt = 0; mt < 2; mt++) {
        int rlo = mw * 32 + mt * 16 + g;
        float xn_lo = xns[rlo];
        float xn_hi = xns[rlo + 8];
        float* out_lo = out + ((size_t)(b * NN + i0 + rlo)) * NN + j0;
        float* out_hi = out_lo + (size_t)8 * NN;
        #pragma unroll
        for (int nt = 0; nt < 8; nt++) {
            int jl = nw * 64 + nt * 8 + tq * 2;
            float yn0 = yns[jl], yn1 = yns[jl + 1];
            float* a4 = acc[mt][nt];
            float2 v;
            v.x = fmaf(-2.f, a4[0], xn_lo + yn0);
            v.y = fmaf(-2.f, a4[1], xn_lo + yn1);
            *(float2*)(out_lo + jl) = v;
            v.x = fmaf(-2.f, a4[2], xn_hi + yn0);
            v.y = fmaf(-2.f, a4[3], xn_hi + yn1);
            *(float2*)(out_hi + jl) = v;
        }
    }
}

extern "C" void kernel_launch(void* const* d_in, const int* in_sizes, int n_in,
                              void* d_out, int out_size) {
    const float* x = (const float*)d_in[0];
    const float* y = (const float*)d_in[1];
    float* out = (float*)d_out;

    cudaFuncSetAttribute(pd_kernel, cudaFuncAttributeMaxDynamicSharedMemorySize,
                         (int)SMEM_BYTES);

    norm_kernel<<<(2 * BB * NN * 32) / 256, 256>>>(x, y);

    dim3 grid(NN / TJ, NN / TI, BB);
    pd_kernel<<<grid, 256, SMEM_BYTES>>>(x, y, out);
}

// round 9
// speedup vs baseline: 1.3384x; 1.0812x over previous
#include <cuda_runtime.h>
#include <cuda_bf16.h>
#include <cstdint>

#define BB 2
#define NN 2048
#define DD 64
#define TI 128
#define TJ 128

// ---------------- smem layout ----------------
#define OFF_XN      0              // 128 floats
#define OFF_YN      512            // 128 floats
#define OFF_TILES   1024
#define SUB_BYTES   (128 * 128)    // one bf16 subtile: 128 rows x 128B (64 bf16)
#define OFF_AXH     (OFF_TILES + 0 * SUB_BYTES)
#define OFF_AXL     (OFF_TILES + 1 * SUB_BYTES)
#define OFF_BYH     (OFF_TILES + 2 * SUB_BYTES)
#define OFF_BYL     (OFF_TILES + 3 * SUB_BYTES)
#define SMEM_BYTES  (OFF_TILES + 4 * SUB_BYTES)   // 66560

__device__ __forceinline__ uint32_t smem_u32(const void* p) {
    uint32_t a;
    asm("{ .reg .u64 t; cvta.to.shared.u64 t, %1; cvt.u32.u64 %0, t; }" : "=r"(a) : "l"(p));
    return a;
}
#define SW128(off) ((off) ^ (((off) >> 3) & 0x70))

__device__ __forceinline__ void ldsm4(uint32_t* r, uint32_t addr) {
    asm volatile("ldmatrix.sync.aligned.m8n8.x4.shared.b16 {%0,%1,%2,%3}, [%4];"
        : "=r"(r[0]), "=r"(r[1]), "=r"(r[2]), "=r"(r[3]) : "r"(addr));
}

__device__ __forceinline__ void mma16816(float* c, const uint32_t* a,
                                         uint32_t b0, uint32_t b1) {
    asm volatile("mma.sync.aligned.m16n8k16.row.col.f32.bf16.bf16.f32 "
        "{%0,%1,%2,%3}, {%4,%5,%6,%7}, {%8,%9}, {%0,%1,%2,%3};"
        : "+f"(c[0]), "+f"(c[1]), "+f"(c[2]), "+f"(c[3])
        : "r"(a[0]), "r"(a[1]), "r"(a[2]), "r"(a[3]), "r"(b0), "r"(b1));
}

// ---------------------------------------------------------------------------
// Single kernel: 128x128 tile per CTA. bf16-split GEMM (K'=192) on HMMA.
// Row norms computed in-CTA during the fill phase (16-lane shfl tree) —
// no separate norm kernel, no global norm buffers.
// ---------------------------------------------------------------------------
__global__ __launch_bounds__(256, 2)
void pd_kernel(const float* __restrict__ x, const float* __restrict__ y,
               float* __restrict__ out) {
    extern __shared__ char smem[];
    uint32_t sb = smem_u32(smem);
    int tid = threadIdx.x;
    int wid = tid >> 5;
    int lane = tid & 31;
    int b = blockIdx.z;
    int i0 = blockIdx.y * TI;
    int j0 = blockIdx.x * TJ;

    float* xns_sm = (float*)(smem + OFF_XN);
    float* yns_sm = (float*)(smem + OFF_YN);

    // ---- fill: LDG fp32 rows -> bf16 h/l subtiles + in-flight row norms ----
    const float4* xg = (const float4*)(x + ((size_t)b * NN + i0) * DD);
    const float4* yg = (const float4*)(y + ((size_t)b * NN + j0) * DD);
    #pragma unroll
    for (int it = 0; it < 8; it++) {
        int idx = tid + it * 256;          // 2048 float4 = 128 rows x 16
        int row = idx >> 4;
        int k4 = (idx & 15) << 2;
        uint32_t off = SW128((uint32_t)(row * 128 + k4 * 2));

        float4 v = xg[idx];
        // norm partial: 16 consecutive lanes own one full row
        float sq = v.x * v.x + v.y * v.y + v.z * v.z + v.w * v.w;
        sq += __shfl_xor_sync(0xffffffffu, sq, 1);
        sq += __shfl_xor_sync(0xffffffffu, sq, 2);
        sq += __shfl_xor_sync(0xffffffffu, sq, 4);
        sq += __shfl_xor_sync(0xffffffffu, sq, 8);
        if ((lane & 15) == 0) xns_sm[row] = sq;

        __nv_bfloat162 h0 = __floats2bfloat162_rn(v.x, v.y);
        __nv_bfloat162 h1 = __floats2bfloat162_rn(v.z, v.w);
        __nv_bfloat162 l0 = __floats2bfloat162_rn(v.x - __bfloat162float(h0.x),
                                                  v.y - __bfloat162float(h0.y));
        __nv_bfloat162 l1 = __floats2bfloat162_rn(v.z - __bfloat162float(h1.x),
                                                  v.w - __bfloat162float(h1.y));
        *(uint2*)(smem + OFF_AXH + off) = make_uint2(*(uint32_t*)&h0, *(uint32_t*)&h1);
        *(uint2*)(smem + OFF_AXL + off) = make_uint2(*(uint32_t*)&l0, *(uint32_t*)&l1);

        float4 w = yg[idx];
        float sw = w.x * w.x + w.y * w.y + w.z * w.z + w.w * w.w;
        sw += __shfl_xor_sync(0xffffffffu, sw, 1);
        sw += __shfl_xor_sync(0xffffffffu, sw, 2);
        sw += __shfl_xor_sync(0xffffffffu, sw, 4);
        sw += __shfl_xor_sync(0xffffffffu, sw, 8);
        if ((lane & 15) == 0) yns_sm[row] = sw;

        __nv_bfloat162 g0 = __floats2bfloat162_rn(w.x, w.y);
        __nv_bfloat162 g1 = __floats2bfloat162_rn(w.z, w.w);
        __nv_bfloat162 m0 = __floats2bfloat162_rn(w.x - __bfloat162float(g0.x),
                                                  w.y - __bfloat162float(g0.y));
        __nv_bfloat162 m1 = __floats2bfloat162_rn(w.z - __bfloat162float(g1.x),
                                                  w.w - __bfloat162float(g1.y));
        *(uint2*)(smem + OFF_BYH + off) = make_uint2(*(uint32_t*)&g0, *(uint32_t*)&g1);
        *(uint2*)(smem + OFF_BYL + off) = make_uint2(*(uint32_t*)&m0, *(uint32_t*)&m1);
    }
    __syncthreads();

    // ---- warp tiling: warp (mw, nw) computes rows mw*32..+31, cols nw*64..+63 ----
    int mw = wid & 3;
    int nw = wid >> 2;

    uint32_t rA[2], mskA[2];
    #pragma unroll
    for (int mt = 0; mt < 2; mt++) {
        uint32_t row = mw * 32 + mt * 16 + (lane & 7) + ((lane >> 3) & 1) * 8;
        rA[mt] = row * 128;
        mskA[mt] = (rA[mt] >> 3) & 0x70;
    }
    uint32_t kA = (lane >> 4) * 16;
    uint32_t rB[4], mskB[4];
    #pragma unroll
    for (int np = 0; np < 4; np++) {
        uint32_t row = nw * 64 + np * 16 + (lane & 7) + ((lane >> 4) & 1) * 8;
        rB[np] = row * 128;
        mskB[np] = (rB[np] >> 3) & 0x70;
    }
    uint32_t kB = ((lane >> 3) & 1) * 16;

    float acc[2][8][4];
    #pragma unroll
    for (int mt = 0; mt < 2; mt++)
        #pragma unroll
        for (int nt = 0; nt < 8; nt++)
            #pragma unroll
            for (int q = 0; q < 4; q++) acc[mt][nt][q] = 0.f;

    // ---- kb-outer mainloop: phase order chosen to hide byl ldsm latency ----
    #pragma unroll
    for (int kb = 0; kb < 4; kb++) {
        uint32_t kbyte = (uint32_t)kb * 32;

        uint32_t axh[2][4], axl[2][4];
        #pragma unroll
        for (int mt = 0; mt < 2; mt++) {
            uint32_t ko = (kbyte + kA);
            ldsm4(axh[mt], sb + OFF_AXH + rA[mt] + (ko ^ mskA[mt]));
            ldsm4(axl[mt], sb + OFF_AXL + rA[mt] + (ko ^ mskA[mt]));
        }
        uint32_t byh[4][4];
        #pragma unroll
        for (int np = 0; np < 4; np++)
            ldsm4(byh[np], sb + OFF_BYH + rB[np] + ((kbyte + kB) ^ mskB[np]));

        // phase 1: xh . yh
        #pragma unroll
        for (int mt = 0; mt < 2; mt++)
            #pragma unroll
            for (int np = 0; np < 4; np++) {
                mma16816(acc[mt][2 * np],     axh[mt], byh[np][0], byh[np][1]);
                mma16816(acc[mt][2 * np + 1], axh[mt], byh[np][2], byh[np][3]);
            }

        // byl loads issued here — covered by phase-3 MMAs below
        uint32_t byl[4][4];
        #pragma unroll
        for (int np = 0; np < 4; np++)
            ldsm4(byl[np], sb + OFF_BYL + rB[np] + ((kbyte + kB) ^ mskB[np]));

        // phase 3: xl . yh (reuses byh, no new loads)
        #pragma unroll
        for (int mt = 0; mt < 2; mt++)
            #pragma unroll
            for (int np = 0; np < 4; np++) {
                mma16816(acc[mt][2 * np],     axl[mt], byh[np][0], byh[np][1]);
                mma16816(acc[mt][2 * np + 1], axl[mt], byh[np][2], byh[np][3]);
            }
        // phase 2: xh . yl
        #pragma unroll
        for (int mt = 0; mt < 2; mt++)
            #pragma unroll
            for (int np = 0; np < 4; np++) {
                mma16816(acc[mt][2 * np],     axh[mt], byl[np][0], byl[np][1]);
                mma16816(acc[mt][2 * np + 1], axh[mt], byl[np][2], byl[np][3]);
            }
    }

    // ---- epilogue: out = xn + yn - 2*dot, direct STG.64 ----
    int g = lane >> 2;
    int tq = lane & 3;

    #pragma unroll
    for (int mt = 0; mt < 2; mt++) {
        int rlo = mw * 32 + mt * 16 + g;
        float xn_lo = xns_sm[rlo];
        float xn_hi = xns_sm[rlo + 8];
        float* out_lo = out + ((size_t)(b * NN + i0 + rlo)) * NN + j0;
        float* out_hi = out_lo + (size_t)8 * NN;
        #pragma unroll
        for (int nt = 0; nt < 8; nt++) {
            int jl = nw * 64 + nt * 8 + tq * 2;
            float yn0 = yns_sm[jl], yn1 = yns_sm[jl + 1];
            float* a4 = acc[mt][nt];
            float2 v;
            v.x = fmaf(-2.f, a4[0], xn_lo + yn0);
            v.y = fmaf(-2.f, a4[1], xn_lo + yn1);
            *(float2*)(out_lo + jl) = v;
            v.x = fmaf(-2.f, a4[2], xn_hi + yn0);
            v.y = fmaf(-2.f, a4[3], xn_hi + yn1);
            *(float2*)(out_hi + jl) = v;
        }
    }
}

extern "C" void kernel_launch(void* const* d_in, const int* in_sizes, int n_in,
                              void* d_out, int out_size) {
    const float* x = (const float*)d_in[0];
    const float* y = (const float*)d_in[1];
    float* out = (float*)d_out;

    cudaFuncSetAttribute(pd_kernel, cudaFuncAttributeMaxDynamicSharedMemorySize,
                         (int)SMEM_BYTES);

    dim3 grid(NN / TJ, NN / TI, BB);
    pd_kernel<<<grid, 256, SMEM_BYTES>>>(x, y, out);
}